// round 16
// baseline (speedup 1.0000x reference)
#include <cuda_runtime.h>
#include <cuda_bf16.h>
#include <math.h>
#include <stdint.h>

#define LEVELS 4
#define KCB    1024
#define DIM    64
#define NVEC   131072
#define CTAV   128
#define NTHR   256
#define CHUNK  128
#define NCHNK  (KCB / CHUNK)          // 8
#define QELEMS ((size_t)NVEC * DIM)
#define MARGIN 0.6f
#define BIAS   1024.0f   // dist' = c2+BIAS-2dot > 0 (needs ||r||*||c|| <= 512)

// ---------------- device scratch ----------------
__device__ double        g_mse[LEVELS];
__device__ int           g_counts[LEVELS * KCB];
__device__ float         g_c2[LEVELS * KCB];    // exact ||c||^2 (duel/rescan)
__device__ float         g_c2b[LEVELS * KCB];   // ||c||^2 + BIAS (key path)
__device__ __nv_bfloat16 g_cbh[LEVELS * KCB * DIM];
__device__ float         g_res[(size_t)NVEC * DIM];  // residual (cold, off-register)
__device__ int           g_done;

// ---------------- SMEM layout (bytes); rows are 128B, XOR-swizzled ----------------
#define SM_AH     0            // 128 rows * 128B = 16384
#define SM_B0     16384        // 16384
#define SM_B1     32768        // 16384
#define SM_C2     49152        // 2 bufs * 128 f32 = 1024
#define SM_IDX    50176        // 128 i32
#define SM_IDX2   50688
#define SM_FLG    51200
#define SM_LIST   51712
#define SM_RST    52224        // 64 f32
#define SM_NL     52480
#define SM_REDK   52488
#define SM_LAST   52496
#define SM_WS     52504        // 8 doubles
#define SMEM_TOTAL 52576       // *4 CTAs = 210KB <= 228KB

// ---------------- helpers ----------------
__device__ __forceinline__ uint32_t smem_u32(const void* p) {
    uint32_t a;
    asm("{ .reg .u64 t; cvta.to.shared.u64 t, %1; cvt.u32.u64 %0, t; }"
        : "=r"(a) : "l"(p));
    return a;
}
__device__ __forceinline__ void ldsm4(uint32_t r[4], uint32_t addr) {
    asm volatile("ldmatrix.sync.aligned.m8n8.x4.shared.b16 {%0,%1,%2,%3}, [%4];"
                 : "=r"(r[0]), "=r"(r[1]), "=r"(r[2]), "=r"(r[3]) : "r"(addr));
}
__device__ __forceinline__ void mma16816(float* d, const uint32_t* a,
                                         uint32_t b0, uint32_t b1) {
    asm volatile(
        "mma.sync.aligned.m16n8k16.row.col.f32.bf16.bf16.f32 "
        "{%0,%1,%2,%3}, {%4,%5,%6,%7}, {%8,%9}, {%0,%1,%2,%3};"
        : "+f"(d[0]), "+f"(d[1]), "+f"(d[2]), "+f"(d[3])
        : "r"(a[0]), "r"(a[1]), "r"(a[2]), "r"(a[3]), "r"(b0), "r"(b1));
}
// zero-C form: D = A*B
__device__ __forceinline__ void mma16816z(float* d, const uint32_t* a,
                                          uint32_t b0, uint32_t b1) {
    asm volatile(
        "mma.sync.aligned.m16n8k16.row.col.f32.bf16.bf16.f32 "
        "{%0,%1,%2,%3}, {%4,%5,%6,%7}, {%8,%9}, {%10,%10,%10,%10};"
        : "=f"(d[0]), "=f"(d[1]), "=f"(d[2]), "=f"(d[3])
        : "r"(a[0]), "r"(a[1]), "r"(a[2]), "r"(a[3]), "r"(b0), "r"(b1),
          "f"(0.f));
}
#define CP16(dst, src) asm volatile("cp.async.cg.shared.global [%0], [%1], 16;" :: "r"(dst), "l"(src))
#define CP_COMMIT()    asm volatile("cp.async.commit_group;" ::: "memory")
#define CP_WAIT0()     asm volatile("cp.async.wait_group 0;" ::: "memory")
#define CP_WAIT1()     asm volatile("cp.async.wait_group 1;" ::: "memory")

// keys: dist' positive -> raw IEEE bits monotone; low 10 bits = index (LOP3)
__device__ __forceinline__ uint32_t dkey(float d, uint32_t idx) {
    return (__float_as_uint(d) & 0xFFFFFC00u) | idx;
}
__device__ __forceinline__ float unkey(uint32_t k) {
    return __uint_as_float(k & 0xFFFFFC00u);   // biased by +BIAS; gaps cancel
}
__device__ __forceinline__ void ins3(uint32_t& K1, uint32_t& K2, uint32_t& K3,
                                     uint32_t g) {
    uint32_t b = umax(K1, g); K1 = umin(K1, g);
    uint32_t d = umax(K2, b); K2 = umin(K2, b);
    K3 = umin(K3, d);
}
__device__ __forceinline__ void ins2(uint32_t& K2, uint32_t& K3, uint32_t g) {
    uint32_t f = umax(K2, g); K2 = umin(K2, g);
    K3 = umin(K3, f);
}
// fold 4 dists into running top-3 keys (true 3-of-4 extraction)
__device__ __forceinline__ void fold4(uint32_t& K1, uint32_t& K2, uint32_t& K3,
                                      float d0, float d1, float d8, float d9,
                                      uint32_t gi) {
    uint32_t k0 = dkey(d0, gi),     k1 = dkey(d1, gi + 1);
    uint32_t k8 = dkey(d8, gi + 8), k9 = dkey(d9, gi + 9);
    uint32_t lo1 = umin(k0, k1), hi1 = umax(k0, k1);
    uint32_t lo2 = umin(k8, k9), hi2 = umax(k8, k9);
    uint32_t g1 = umin(lo1, lo2);
    uint32_t m  = umax(lo1, lo2), n = umin(hi1, hi2);
    uint32_t g2 = umin(m, n);
    uint32_t g3 = umin(umax(m, n), umax(hi1, hi2));
    ins3(K1, K2, K3, g1);
    ins2(K2, K3, g2);
    K3 = umin(K3, g3);
}
__device__ __forceinline__ void lanemerge(uint32_t& K1, uint32_t& K2,
                                          uint32_t& K3, int mx) {
    uint32_t o1 = __shfl_xor_sync(0xffffffffu, K1, mx);
    uint32_t o2 = __shfl_xor_sync(0xffffffffu, K2, mx);
    uint32_t o3 = __shfl_xor_sync(0xffffffffu, K3, mx);
    ins3(K1, K2, K3, o1);
    ins2(K2, K3, o2);
    K3 = umin(K3, o3);
}
__device__ __forceinline__ bool lexless(float v1, int j1, float v2, int j2) {
    return v1 < v2 || (v1 == v2 && j1 < j2);
}

// ---------------- prep kernel ----------------
__global__ void prep_kernel(const float* __restrict__ cb) {
    int t = blockIdx.x * blockDim.x + threadIdx.x;
    if (t == 0) g_done = 0;
    if (t < LEVELS) g_mse[t] = 0.0;
    if (t < LEVELS * KCB) {
        g_counts[t] = 0;
        const float* v = cb + (size_t)t * DIM;
        __nv_bfloat16* dh = g_cbh + (size_t)t * DIM;
        float s = 0.f;
        #pragma unroll
        for (int d = 0; d < DIM; ++d) {
            float f = v[d];
            s += f * f;
            dh[d] = __float2bfloat16(f);
        }
        g_c2[t]  = s;
        g_c2b[t] = s + BIAS;
    }
}

// ---------------- main kernel ----------------
__global__ __launch_bounds__(NTHR, 4)
void rvq_mma_kernel(const float* __restrict__ x,
                    const float* __restrict__ cb,
                    float* __restrict__ out) {
    extern __shared__ char smem[];
    const uint32_t sb = smem_u32(smem);
    const int tid  = threadIdx.x;
    const int lane = tid & 31, warp = tid >> 5;
    const int v = tid >> 1, h = tid & 1;
    const size_t n0 = (size_t)blockIdx.x * CTAV;
    const size_t roff = (n0 + v) * DIM + h * 32;   // this thread's residual slice

    int*   sidx  = (int*)(smem + SM_IDX);
    int*   sidx2 = (int*)(smem + SM_IDX2);
    int*   sflg  = (int*)(smem + SM_FLG);
    int*   list  = (int*)(smem + SM_LIST);
    float* rstage = (float*)(smem + SM_RST);
    int*   nlist = (int*)(smem + SM_NL);
    unsigned long long* redk = (unsigned long long*)(smem + SM_REDK);

    // ---- pre-stage level-0 A from x (residual lives OFF registers) ----
    {
        const float4* xp = (const float4*)(x + roff);
        #pragma unroll
        for (int i = 0; i < 8; ++i) {
            float4 t4 = xp[i];
            float p0[4] = {t4.x, t4.y, t4.z, t4.w};
            #pragma unroll
            for (int j = 0; j < 2; ++j) {
                int ip = 2 * i + j;   // u32-pair index 0..15
                __nv_bfloat16 h0 = __float2bfloat16(p0[2*j]);
                __nv_bfloat16 h1 = __float2bfloat16(p0[2*j + 1]);
                uint32_t wh = (uint32_t)__bfloat16_as_ushort(h0) |
                              ((uint32_t)__bfloat16_as_ushort(h1) << 16);
                int chunk = (h * 4 + (ip >> 2)) ^ (v & 7);
                int off = v * 128 + chunk * 16 + (ip & 3) * 4;
                *(uint32_t*)(smem + SM_AH + off) = wh;
            }
        }
    }

    for (int l = 0; l < LEVELS; ++l) {
        const float* rsrc = (l == 0) ? (x + roff) : (g_res + roff);
        if (tid == 0) *nlist = 0;

        // ---- prefetch B chunk 0 (swizzled stores) ----
        {
            const float4* srh = (const float4*)(g_cbh + (size_t)l * KCB * DIM);
            #pragma unroll
            for (int g = tid; g < CHUNK * 8; g += NTHR) {
                uint32_t dst = (uint32_t)(((g & ~7) + ((g ^ (g >> 3)) & 7)) * 16);
                CP16(sb + SM_B0 + dst, srh + g);
            }
            if (tid < 32)
                CP16(sb + SM_C2 + tid * 16, (const float4*)(g_c2b + l * KCB) + tid);
            CP_COMMIT();
        }
        __syncthreads();

        // ---- A fragments for the level (swizzle-aware) ----
        uint32_t Ah[4][4];
        {
            int r7   = lane >> 2;
            int rowA = warp * 16 + r7;
            int q4   = (lane & 3) * 4;
            #pragma unroll
            for (int ks = 0; ks < 4; ++ks) {
                int ch0 = (ks * 2)     ^ r7;
                int ch1 = (ks * 2 + 1) ^ r7;
                int o00 = rowA * 128 + ch0 * 16 + q4;
                int o01 = rowA * 128 + ch1 * 16 + q4;
                Ah[ks][0] = *(const uint32_t*)(smem + SM_AH + o00);
                Ah[ks][1] = *(const uint32_t*)(smem + SM_AH + o00 + 1024);
                Ah[ks][2] = *(const uint32_t*)(smem + SM_AH + o01);
                Ah[ks][3] = *(const uint32_t*)(smem + SM_AH + o01 + 1024);
            }
        }

        uint32_t Ka1 = 0xFFFFFFFFu, Ka2 = 0xFFFFFFFFu, Ka3 = 0xFFFFFFFFu;
        uint32_t Kb1 = 0xFFFFFFFFu, Kb2 = 0xFFFFFFFFu, Kb3 = 0xFFFFFFFFu;

        int buf = 0;
        for (int ci = 0; ci < NCHNK; ++ci) {
            if (ci < NCHNK - 1) {
                const float4* srh = (const float4*)
                    (g_cbh + ((size_t)l * KCB + (ci + 1) * CHUNK) * DIM);
                uint32_t bdst = sb + (buf ? SM_B0 : SM_B1);
                #pragma unroll
                for (int g = tid; g < CHUNK * 8; g += NTHR) {
                    uint32_t dst = (uint32_t)(((g & ~7) + ((g ^ (g >> 3)) & 7)) * 16);
                    CP16(bdst + dst, srh + g);
                }
                if (tid < 32)
                    CP16(sb + SM_C2 + (buf ^ 1) * 512 + tid * 16,
                         (const float4*)(g_c2b + l * KCB + (ci + 1) * CHUNK) + tid);
                CP_COMMIT();
                CP_WAIT1();
            } else {
                CP_WAIT0();
            }
            __syncthreads();

            const uint32_t bbase = sb + (buf ? SM_B1 : SM_B0);
            const float* c2s = (const float*)(smem + SM_C2 + buf * 512);
            const int c0 = ci * CHUNK;

            #pragma unroll 2
            for (int gp = 0; gp < 8; ++gp) {
                // (1) all LDSMs for this gp
                uint32_t bf[16];
                {
                    int l7 = lane & 7;
                    uint32_t rowb = (uint32_t)((gp * 16 + l7) * 128);
                    uint32_t sw   = (uint32_t)((((lane >> 3) ^ l7) & 7) * 16);
                    ldsm4(bf,      bbase + rowb + sw);
                    ldsm4(bf + 4,  bbase + rowb + sw + 1024);
                    ldsm4(bf + 8,  bbase + rowb + (sw ^ 64));
                    ldsm4(bf + 12, bbase + rowb + (sw ^ 64) + 1024);
                }
                // (2) biased c2 for this gp
                int nb = gp * 16 + (lane & 3) * 2;
                float2 a2 = *(const float2*)(c2s + nb);
                float2 b2 = *(const float2*)(c2s + nb + 8);
                // (3) MMAs — 4-deep chains, zero-C first (no D init)
                float D[8];
                mma16816z(&D[0], Ah[0], bf[0], bf[1]);
                mma16816 (&D[0], Ah[1], bf[2], bf[3]);
                mma16816 (&D[0], Ah[2], bf[8], bf[9]);
                mma16816 (&D[0], Ah[3], bf[10], bf[11]);
                mma16816z(&D[4], Ah[0], bf[4], bf[5]);
                mma16816 (&D[4], Ah[1], bf[6], bf[7]);
                mma16816 (&D[4], Ah[2], bf[12], bf[13]);
                mma16816 (&D[4], Ah[3], bf[14], bf[15]);
                // (4) fold immediately (cross-warp issue covers the latency)
                {
                    uint32_t gi = (uint32_t)(c0 + nb);
                    fold4(Ka1, Ka2, Ka3,
                          fmaf(-2.f, D[0], a2.x), fmaf(-2.f, D[1], a2.y),
                          fmaf(-2.f, D[4], b2.x), fmaf(-2.f, D[5], b2.y), gi);
                    fold4(Kb1, Kb2, Kb3,
                          fmaf(-2.f, D[2], a2.x), fmaf(-2.f, D[3], a2.y),
                          fmaf(-2.f, D[6], b2.x), fmaf(-2.f, D[7], b2.y), gi);
                }
            }
            __syncthreads();
            buf ^= 1;
        }

        // ---- merge across the 4 lanes of each row quad (key space) ----
        lanemerge(Ka1, Ka2, Ka3, 1);
        lanemerge(Ka1, Ka2, Ka3, 2);
        lanemerge(Kb1, Kb2, Kb3, 1);
        lanemerge(Kb1, Kb2, Kb3, 2);
        if ((lane & 3) == 0) {
            int vA = warp * 16 + (lane >> 2), vB = vA + 8;
            float m1a = unkey(Ka1), m2a = unkey(Ka2), m3a = unkey(Ka3);
            float m1b = unkey(Kb1), m2b = unkey(Kb2), m3b = unkey(Kb3);
            sidx[vA] = (int)(Ka1 & 1023u); sidx2[vA] = (int)(Ka2 & 1023u);
            sidx[vB] = (int)(Kb1 & 1023u); sidx2[vB] = (int)(Kb2 & 1023u);
            int fA = (m3a - m1a < MARGIN) ? 2 : ((m2a - m1a < MARGIN) ? 1 : 0);
            int fB = (m3b - m1b < MARGIN) ? 2 : ((m2b - m1b < MARGIN) ? 1 : 0);
            sflg[vA] = fA; sflg[vB] = fB;
            if (fA == 2) { int p = atomicAdd(nlist, 1); list[p] = vA; }
            if (fB == 2) { int p = atomicAdd(nlist, 1); list[p] = vB; }
        }
        __syncthreads();

        // ---- full exact rescans (rare) ----
        int nf = *nlist;
        for (int f = 0; f < nf; ++f) {
            int vr = list[f];
            if (tid == 0) *redk = ~0ull;
            if (v == vr) {
                const float4* rp4 = (const float4*)rsrc;
                #pragma unroll
                for (int i = 0; i < 8; ++i)
                    *(float4*)(rstage + h * 32 + 4*i) = rp4[i];
            }
            __syncthreads();
            unsigned long long bk = ~0ull;
            #pragma unroll 1
            for (int c = tid; c < KCB; c += NTHR) {
                const float4* cw = (const float4*)(cb + ((size_t)l * KCB + c) * DIM);
                const float4* rp = (const float4*)rstage;
                float s = 0.f;
                #pragma unroll
                for (int i = 0; i < 16; ++i) {
                    float4 a = rp[i], bq = cw[i];
                    s += a.x*bq.x + a.y*bq.y + a.z*bq.z + a.w*bq.w;
                }
                float dist = fmaf(-2.f, s, g_c2[l * KCB + c]);
                uint32_t fb = __float_as_uint(dist);
                fb ^= (fb & 0x80000000u) ? 0xFFFFFFFFu : 0x80000000u;
                unsigned long long key = ((unsigned long long)fb << 32) | (unsigned)c;
                if (key < bk) bk = key;
            }
            atomicMin(redk, bk);
            __syncthreads();
            if (tid == 0) sidx[vr] = (int)(*redk & 0xffffffffu);
            __syncthreads();
        }

        // ---- exact duels (parallel, per-vector owner pair) ----
        int idx = sidx[v];
        int fl  = sflg[v];
        float sA = 0.f, sB = 0.f;
        int iA = idx, iB = sidx2[v];
        if (fl == 1) {
            const float4* rp4 = (const float4*)rsrc;
            const float4* ca = (const float4*)(cb + ((size_t)l * KCB + iA) * DIM + h * 32);
            const float4* cbq = (const float4*)(cb + ((size_t)l * KCB + iB) * DIM + h * 32);
            #pragma unroll
            for (int i = 0; i < 8; ++i) {
                float4 rv = rp4[i], a = ca[i], b = cbq[i];
                sA += rv.x*a.x + rv.y*a.y + rv.z*a.z + rv.w*a.w;
                sB += rv.x*b.x + rv.y*b.y + rv.z*b.z + rv.w*b.w;
            }
        }
        sA += __shfl_xor_sync(0xffffffffu, sA, 1);
        sB += __shfl_xor_sync(0xffffffffu, sB, 1);
        if (fl == 1) {
            float dA = fmaf(-2.f, sA, g_c2[l * KCB + iA]);
            float dB = fmaf(-2.f, sB, g_c2[l * KCB + iB]);
            idx = lexless(dB, iB, dA, iA) ? iB : iA;
        }

        // ---- commit: r_new = r - q; write g_res / stage next A / out staging ----
        {
            const float4* rp4 = (const float4*)rsrc;
            const float4* q4  = (const float4*)(cb + ((size_t)l * KCB + idx) * DIM + h * 32);
            float rn[32];
            float sse = 0.f;
            #pragma unroll
            for (int i = 0; i < 8; ++i) {
                float4 rv = rp4[i], qv = q4[i];
                rn[4*i]   = rv.x - qv.x; rn[4*i+1] = rv.y - qv.y;
                rn[4*i+2] = rv.z - qv.z; rn[4*i+3] = rv.w - qv.w;
                sse += rn[4*i]*rn[4*i] + rn[4*i+1]*rn[4*i+1]
                     + rn[4*i+2]*rn[4*i+2] + rn[4*i+3]*rn[4*i+3];
            }
            if (l < LEVELS - 1) {
                float4* dst = (float4*)(g_res + roff);
                #pragma unroll
                for (int i = 0; i < 8; ++i)
                    dst[i] = make_float4(rn[4*i], rn[4*i+1], rn[4*i+2], rn[4*i+3]);
                // fused: stage A for next level
                #pragma unroll
                for (int ip = 0; ip < 16; ++ip) {
                    __nv_bfloat16 h0 = __float2bfloat16(rn[2*ip]);
                    __nv_bfloat16 h1 = __float2bfloat16(rn[2*ip+1]);
                    uint32_t wh = (uint32_t)__bfloat16_as_ushort(h0) |
                                  ((uint32_t)__bfloat16_as_ushort(h1) << 16);
                    int chunk = (h * 4 + (ip >> 2)) ^ (v & 7);
                    int off = v * 128 + chunk * 16 + (ip & 3) * 4;
                    *(uint32_t*)(smem + SM_AH + off) = wh;
                }
            } else {
                // last level: stage r_final in smem for coalesced output
                float* rs = (float*)(smem + SM_B0);
                #pragma unroll
                for (int i = 0; i < 8; ++i)
                    *(float4*)(rs + v * 64 + h * 32 + 4*i) =
                        make_float4(rn[4*i], rn[4*i+1], rn[4*i+2], rn[4*i+3]);
            }
            double ds = (double)sse;
            #pragma unroll
            for (int o = 16; o; o >>= 1) ds += __shfl_down_sync(0xffffffffu, ds, o);
            if (lane == 0) atomicAdd(&g_mse[l], ds);
        }
        if (h == 0) {
            atomicAdd(&g_counts[l * KCB + idx], 1);
            out[QELEMS + (size_t)l * NVEC + n0 + v] = (float)idx;
        }
        __syncthreads();
    }

    // ---- quantized = x - final residual (coalesced via B0+B1 staging) ----
    {
        const float4* xp4 = (const float4*)(x + n0 * DIM);
        const float4* rs4 = (const float4*)(smem + SM_B0);
        float4*       op4 = (float4*)(out + n0 * DIM);
        #pragma unroll
        for (int g = tid; g < CTAV * 16; g += NTHR) {
            float4 xv = xp4[g], rv = rs4[g];
            op4[g] = make_float4(xv.x - rv.x, xv.y - rv.y,
                                 xv.z - rv.z, xv.w - rv.w);
        }
    }

    // ---- last CTA runs finalize ----
    int* slast = (int*)(smem + SM_LAST);
    if (tid == 0) {
        __threadfence();
        *slast = (atomicAdd(&g_done, 1) == (int)gridDim.x - 1) ? 1 : 0;
    }
    __syncthreads();
    if (*slast) {
        __threadfence();
        double* ws = (double*)(smem + SM_WS);
        double total = 0.0;
        for (int l = 0; l < LEVELS; ++l) {
            float esum = 0.f;
            for (int i = tid; i < KCB; i += NTHR) {
                float p = (float)g_counts[l * KCB + i] / (float)NVEC;
                esum += -(p * logf(p + 1e-10f));
            }
            double e = (double)esum;
            #pragma unroll
            for (int o = 16; o; o >>= 1) e += __shfl_down_sync(0xffffffffu, e, o);
            if ((tid & 31) == 0) ws[tid >> 5] = e;
            __syncthreads();
            if (tid == 0) {
                double ent = 0.0;
                #pragma unroll
                for (int w = 0; w < 8; ++w) ent += ws[w];
                total += 1.25 * (g_mse[l] / ((double)NVEC * DIM)) + 0.1 * ent;
            }
            __syncthreads();
        }
        if (tid == 0) out[QELEMS + (size_t)LEVELS * NVEC] = (float)total;
    }
}

extern "C" void kernel_launch(void* const* d_in, const int* in_sizes, int n_in,
                              void* d_out, int out_size) {
    const float* x  = (const float*)d_in[0];
    const float* cb = (const float*)d_in[1];
    float* out = (float*)d_out;

    cudaFuncSetAttribute(rvq_mma_kernel,
                         cudaFuncAttributeMaxDynamicSharedMemorySize, SMEM_TOTAL);

    prep_kernel<<<16, 256>>>(cb);
    rvq_mma_kernel<<<NVEC / CTAV, NTHR, SMEM_TOTAL>>>(x, cb, out);
}

// round 17
// speedup vs baseline: 1.1488x; 1.1488x over previous
#include <cuda_runtime.h>
#include <cuda_bf16.h>
#include <math.h>
#include <stdint.h>

#define LEVELS 4
#define KCB    1024
#define DIM    64
#define NVEC   131072
#define CTAV   256            // one vector per thread
#define NTHR   256
#define CHUNK  128
#define NCHNK  (KCB / CHUNK)          // 8
#define QELEMS ((size_t)NVEC * DIM)
#define MARGIN 0.6f
#define BIAS   1024.0f   // dist' = c2+BIAS-2dot > 0 (needs ||r||*||c|| <= 512)

// ---------------- device scratch ----------------
__device__ double        g_mse[LEVELS];
__device__ int           g_counts[LEVELS * KCB];
__device__ float         g_c2[LEVELS * KCB];    // exact ||c||^2 (duel/rescan)
__device__ float         g_c2b[LEVELS * KCB];   // ||c||^2 + BIAS (key path)
__device__ __nv_bfloat16 g_cbh[LEVELS * KCB * DIM];
__device__ float         g_res[(size_t)NVEC * DIM];  // residual (off-register)

// ---------------- SMEM layout (bytes); rows are 128B, XOR-swizzled ----------------
#define SM_AH     0            // 256 rows * 128B = 32768
#define SM_B0     32768        // 16384
#define SM_B1     49152        // 16384
#define SM_C2     65536        // 2 bufs * 128 f32 = 1024
#define SM_IDX    66560        // 256 i32
#define SM_IDX2   67584
#define SM_FLG    68608
#define SM_LIST   69632
#define SM_RST    70656        // 64 f32
#define SM_NL     70912
#define SM_REDK   70920
#define SMEM_TOTAL 70944       // *2 CTAs = 142KB <= 228KB

// ---------------- helpers ----------------
__device__ __forceinline__ uint32_t smem_u32(const void* p) {
    uint32_t a;
    asm("{ .reg .u64 t; cvta.to.shared.u64 t, %1; cvt.u32.u64 %0, t; }"
        : "=r"(a) : "l"(p));
    return a;
}
__device__ __forceinline__ void ldsm4(uint32_t r[4], uint32_t addr) {
    asm volatile("ldmatrix.sync.aligned.m8n8.x4.shared.b16 {%0,%1,%2,%3}, [%4];"
                 : "=r"(r[0]), "=r"(r[1]), "=r"(r[2]), "=r"(r[3]) : "r"(addr));
}
__device__ __forceinline__ void mma16816(float* d, const uint32_t* a,
                                         uint32_t b0, uint32_t b1) {
    asm volatile(
        "mma.sync.aligned.m16n8k16.row.col.f32.bf16.bf16.f32 "
        "{%0,%1,%2,%3}, {%4,%5,%6,%7}, {%8,%9}, {%0,%1,%2,%3};"
        : "+f"(d[0]), "+f"(d[1]), "+f"(d[2]), "+f"(d[3])
        : "r"(a[0]), "r"(a[1]), "r"(a[2]), "r"(a[3]), "r"(b0), "r"(b1));
}
// zero-C form: D = A*B
__device__ __forceinline__ void mma16816z(float* d, const uint32_t* a,
                                          uint32_t b0, uint32_t b1) {
    asm volatile(
        "mma.sync.aligned.m16n8k16.row.col.f32.bf16.bf16.f32 "
        "{%0,%1,%2,%3}, {%4,%5,%6,%7}, {%8,%9}, {%10,%10,%10,%10};"
        : "=f"(d[0]), "=f"(d[1]), "=f"(d[2]), "=f"(d[3])
        : "r"(a[0]), "r"(a[1]), "r"(a[2]), "r"(a[3]), "r"(b0), "r"(b1),
          "f"(0.f));
}
#define CP16(dst, src) asm volatile("cp.async.cg.shared.global [%0], [%1], 16;" :: "r"(dst), "l"(src))
#define CP_COMMIT()    asm volatile("cp.async.commit_group;" ::: "memory")
#define CP_WAIT0()     asm volatile("cp.async.wait_group 0;" ::: "memory")
#define CP_WAIT1()     asm volatile("cp.async.wait_group 1;" ::: "memory")

// keys: dist' positive -> raw IEEE bits monotone; low 10 bits = index (LOP3)
__device__ __forceinline__ uint32_t dkey(float d, uint32_t idx) {
    return (__float_as_uint(d) & 0xFFFFFC00u) | idx;
}
__device__ __forceinline__ float unkey(uint32_t k) {
    return __uint_as_float(k & 0xFFFFFC00u);
}
__device__ __forceinline__ void ins3(uint32_t& K1, uint32_t& K2, uint32_t& K3,
                                     uint32_t g) {
    uint32_t b = umax(K1, g); K1 = umin(K1, g);
    uint32_t d = umax(K2, b); K2 = umin(K2, b);
    K3 = umin(K3, d);
}
__device__ __forceinline__ void ins2(uint32_t& K2, uint32_t& K3, uint32_t g) {
    uint32_t f = umax(K2, g); K2 = umin(K2, g);
    K3 = umin(K3, f);
}
// fold 4 dists into running top-3 keys (true 3-of-4 extraction)
__device__ __forceinline__ void fold4(uint32_t& K1, uint32_t& K2, uint32_t& K3,
                                      float d0, float d1, float d8, float d9,
                                      uint32_t gi) {
    uint32_t k0 = dkey(d0, gi),     k1 = dkey(d1, gi + 1);
    uint32_t k8 = dkey(d8, gi + 8), k9 = dkey(d9, gi + 9);
    uint32_t lo1 = umin(k0, k1), hi1 = umax(k0, k1);
    uint32_t lo2 = umin(k8, k9), hi2 = umax(k8, k9);
    uint32_t g1 = umin(lo1, lo2);
    uint32_t m  = umax(lo1, lo2), n = umin(hi1, hi2);
    uint32_t g2 = umin(m, n);
    uint32_t g3 = umin(umax(m, n), umax(hi1, hi2));
    ins3(K1, K2, K3, g1);
    ins2(K2, K3, g2);
    K3 = umin(K3, g3);
}
__device__ __forceinline__ void lanemerge(uint32_t& K1, uint32_t& K2,
                                          uint32_t& K3, int mx) {
    uint32_t o1 = __shfl_xor_sync(0xffffffffu, K1, mx);
    uint32_t o2 = __shfl_xor_sync(0xffffffffu, K2, mx);
    uint32_t o3 = __shfl_xor_sync(0xffffffffu, K3, mx);
    ins3(K1, K2, K3, o1);
    ins2(K2, K3, o2);
    K3 = umin(K3, o3);
}
__device__ __forceinline__ bool lexless(float v1, int j1, float v2, int j2) {
    return v1 < v2 || (v1 == v2 && j1 < j2);
}

// ---------------- prep kernel ----------------
__global__ void prep_kernel(const float* __restrict__ cb) {
    int t = blockIdx.x * blockDim.x + threadIdx.x;
    if (t < LEVELS) g_mse[t] = 0.0;
    if (t < LEVELS * KCB) {
        g_counts[t] = 0;
        const float* v = cb + (size_t)t * DIM;
        __nv_bfloat16* dh = g_cbh + (size_t)t * DIM;
        float s = 0.f;
        #pragma unroll
        for (int d = 0; d < DIM; ++d) {
            float f = v[d];
            s += f * f;
            dh[d] = __float2bfloat16(f);
        }
        g_c2[t]  = s;
        g_c2b[t] = s + BIAS;
    }
}

// ---------------- main kernel ----------------
__global__ __launch_bounds__(NTHR, 2)
void rvq_mma_kernel(const float* __restrict__ x,
                    const float* __restrict__ cb,
                    float* __restrict__ out) {
    extern __shared__ char smem[];
    const uint32_t sb = smem_u32(smem);
    const int tid  = threadIdx.x;
    const int lane = tid & 31, warp = tid >> 5;
    const int v = tid;                        // one vector per thread
    const size_t n0 = (size_t)blockIdx.x * CTAV;
    const size_t roff = (n0 + v) * DIM;

    int*   sidx  = (int*)(smem + SM_IDX);
    int*   sidx2 = (int*)(smem + SM_IDX2);
    int*   sflg  = (int*)(smem + SM_FLG);
    int*   list  = (int*)(smem + SM_LIST);
    float* rstage = (float*)(smem + SM_RST);
    int*   nlist = (int*)(smem + SM_NL);
    unsigned long long* redk = (unsigned long long*)(smem + SM_REDK);

    // ---- pre-stage level-0 A from x ----
    {
        const float4* xp = (const float4*)(x + roff);
        #pragma unroll
        for (int i = 0; i < 16; ++i) {
            float4 t4 = xp[i];
            #pragma unroll
            for (int j = 0; j < 2; ++j) {
                int ip = 2 * i + j;   // u32-pair index 0..31
                float lo = j ? t4.z : t4.x, hi = j ? t4.w : t4.y;
                __nv_bfloat16 h0 = __float2bfloat16(lo);
                __nv_bfloat16 h1 = __float2bfloat16(hi);
                uint32_t wh = (uint32_t)__bfloat16_as_ushort(h0) |
                              ((uint32_t)__bfloat16_as_ushort(h1) << 16);
                int chunk = (ip >> 2) ^ (v & 7);
                *(uint32_t*)(smem + SM_AH + v * 128 + chunk * 16 + (ip & 3) * 4) = wh;
            }
        }
    }

    for (int l = 0; l < LEVELS; ++l) {
        const float* rsrc = (l == 0) ? (x + roff) : (g_res + roff);
        if (tid == 0) *nlist = 0;

        // ---- prefetch B chunk 0 (swizzled stores) ----
        {
            const float4* srh = (const float4*)(g_cbh + (size_t)l * KCB * DIM);
            #pragma unroll
            for (int g = tid; g < CHUNK * 8; g += NTHR) {
                uint32_t dst = (uint32_t)(((g & ~7) + ((g ^ (g >> 3)) & 7)) * 16);
                CP16(sb + SM_B0 + dst, srh + g);
            }
            if (tid < 32)
                CP16(sb + SM_C2 + tid * 16, (const float4*)(g_c2b + l * KCB) + tid);
            CP_COMMIT();
        }
        __syncthreads();

        // ---- A fragments: TWO 16-row sets per warp (32 rows total) ----
        uint32_t Ah[2][4][4];
        {
            int r7 = lane >> 2;
            int q4 = (lane & 3) * 4;
            #pragma unroll
            for (int s = 0; s < 2; ++s) {
                int rowA = warp * 32 + s * 16 + r7;
                #pragma unroll
                for (int ks = 0; ks < 4; ++ks) {
                    int ch0 = (ks * 2)     ^ r7;
                    int ch1 = (ks * 2 + 1) ^ r7;
                    int o00 = rowA * 128 + ch0 * 16 + q4;
                    int o01 = rowA * 128 + ch1 * 16 + q4;
                    Ah[s][ks][0] = *(const uint32_t*)(smem + SM_AH + o00);
                    Ah[s][ks][1] = *(const uint32_t*)(smem + SM_AH + o00 + 1024);
                    Ah[s][ks][2] = *(const uint32_t*)(smem + SM_AH + o01);
                    Ah[s][ks][3] = *(const uint32_t*)(smem + SM_AH + o01 + 1024);
                }
            }
        }

        uint32_t Ka1 = 0xFFFFFFFFu, Ka2 = 0xFFFFFFFFu, Ka3 = 0xFFFFFFFFu;
        uint32_t Kb1 = 0xFFFFFFFFu, Kb2 = 0xFFFFFFFFu, Kb3 = 0xFFFFFFFFu;
        uint32_t Kc1 = 0xFFFFFFFFu, Kc2 = 0xFFFFFFFFu, Kc3 = 0xFFFFFFFFu;
        uint32_t Kd1 = 0xFFFFFFFFu, Kd2 = 0xFFFFFFFFu, Kd3 = 0xFFFFFFFFu;

        int buf = 0;
        for (int ci = 0; ci < NCHNK; ++ci) {
            if (ci < NCHNK - 1) {
                const float4* srh = (const float4*)
                    (g_cbh + ((size_t)l * KCB + (ci + 1) * CHUNK) * DIM);
                uint32_t bdst = sb + (buf ? SM_B0 : SM_B1);
                #pragma unroll
                for (int g = tid; g < CHUNK * 8; g += NTHR) {
                    uint32_t dst = (uint32_t)(((g & ~7) + ((g ^ (g >> 3)) & 7)) * 16);
                    CP16(bdst + dst, srh + g);
                }
                if (tid < 32)
                    CP16(sb + SM_C2 + (buf ^ 1) * 512 + tid * 16,
                         (const float4*)(g_c2b + l * KCB + (ci + 1) * CHUNK) + tid);
                CP_COMMIT();
                CP_WAIT1();
            } else {
                CP_WAIT0();
            }
            __syncthreads();

            const uint32_t bbase = sb + (buf ? SM_B1 : SM_B0);
            const float* c2s = (const float*)(smem + SM_C2 + buf * 512);
            const int c0 = ci * CHUNK;

            #pragma unroll 2
            for (int gp = 0; gp < 8; ++gp) {
                // (1) LDSMs — B reused across BOTH A sets (2x fewer smem reads/FLOP)
                uint32_t bf[16];
                {
                    int l7 = lane & 7;
                    uint32_t rowb = (uint32_t)((gp * 16 + l7) * 128);
                    uint32_t sw   = (uint32_t)((((lane >> 3) ^ l7) & 7) * 16);
                    ldsm4(bf,      bbase + rowb + sw);
                    ldsm4(bf + 4,  bbase + rowb + sw + 1024);
                    ldsm4(bf + 8,  bbase + rowb + (sw ^ 64));
                    ldsm4(bf + 12, bbase + rowb + (sw ^ 64) + 1024);
                }
                int nb = gp * 16 + (lane & 3) * 2;
                float2 a2 = *(const float2*)(c2s + nb);
                float2 b2 = *(const float2*)(c2s + nb + 8);
                uint32_t gi = (uint32_t)(c0 + nb);
                // (2) A set 0: 8 MMAs (2x 2-deep chains + FADD merge), fold
                {
                    float D[8], T[4];
                    mma16816z(&D[0], Ah[0][0], bf[0], bf[1]);
                    mma16816 (&D[0], Ah[0][1], bf[2], bf[3]);
                    mma16816z(T,     Ah[0][2], bf[8], bf[9]);
                    mma16816 (T,     Ah[0][3], bf[10], bf[11]);
                    #pragma unroll
                    for (int q = 0; q < 4; ++q) D[q] += T[q];
                    mma16816z(&D[4], Ah[0][0], bf[4], bf[5]);
                    mma16816 (&D[4], Ah[0][1], bf[6], bf[7]);
                    mma16816z(T,     Ah[0][2], bf[12], bf[13]);
                    mma16816 (T,     Ah[0][3], bf[14], bf[15]);
                    #pragma unroll
                    for (int q = 0; q < 4; ++q) D[4 + q] += T[q];
                    fold4(Ka1, Ka2, Ka3,
                          fmaf(-2.f, D[0], a2.x), fmaf(-2.f, D[1], a2.y),
                          fmaf(-2.f, D[4], b2.x), fmaf(-2.f, D[5], b2.y), gi);
                    fold4(Kb1, Kb2, Kb3,
                          fmaf(-2.f, D[2], a2.x), fmaf(-2.f, D[3], a2.y),
                          fmaf(-2.f, D[6], b2.x), fmaf(-2.f, D[7], b2.y), gi);
                }
                // (3) A set 1: same B fragments
                {
                    float D[8], T[4];
                    mma16816z(&D[0], Ah[1][0], bf[0], bf[1]);
                    mma16816 (&D[0], Ah[1][1], bf[2], bf[3]);
                    mma16816z(T,     Ah[1][2], bf[8], bf[9]);
                    mma16816 (T,     Ah[1][3], bf[10], bf[11]);
                    #pragma unroll
                    for (int q = 0; q < 4; ++q) D[q] += T[q];
                    mma16816z(&D[4], Ah[1][0], bf[4], bf[5]);
                    mma16816 (&D[4], Ah[1][1], bf[6], bf[7]);
                    mma16816z(T,     Ah[1][2], bf[12], bf[13]);
                    mma16816 (T,     Ah[1][3], bf[14], bf[15]);
                    #pragma unroll
                    for (int q = 0; q < 4; ++q) D[4 + q] += T[q];
                    fold4(Kc1, Kc2, Kc3,
                          fmaf(-2.f, D[0], a2.x), fmaf(-2.f, D[1], a2.y),
                          fmaf(-2.f, D[4], b2.x), fmaf(-2.f, D[5], b2.y), gi);
                    fold4(Kd1, Kd2, Kd3,
                          fmaf(-2.f, D[2], a2.x), fmaf(-2.f, D[3], a2.y),
                          fmaf(-2.f, D[6], b2.x), fmaf(-2.f, D[7], b2.y), gi);
                }
            }
            __syncthreads();
            buf ^= 1;
        }

        // ---- merge across the 4 lanes of each row quad ----
        lanemerge(Ka1, Ka2, Ka3, 1); lanemerge(Ka1, Ka2, Ka3, 2);
        lanemerge(Kb1, Kb2, Kb3, 1); lanemerge(Kb1, Kb2, Kb3, 2);
        lanemerge(Kc1, Kc2, Kc3, 1); lanemerge(Kc1, Kc2, Kc3, 2);
        lanemerge(Kd1, Kd2, Kd3, 1); lanemerge(Kd1, Kd2, Kd3, 2);
        if ((lane & 3) == 0) {
            int r8 = lane >> 2;
            int base = warp * 32 + r8;
            uint32_t K1s[4] = {Ka1, Kb1, Kc1, Kd1};
            uint32_t K2s[4] = {Ka2, Kb2, Kc2, Kd2};
            uint32_t K3s[4] = {Ka3, Kb3, Kc3, Kd3};
            int vs[4] = {base, base + 8, base + 16, base + 24};
            #pragma unroll
            for (int q = 0; q < 4; ++q) {
                float m1 = unkey(K1s[q]), m2 = unkey(K2s[q]), m3 = unkey(K3s[q]);
                sidx[vs[q]]  = (int)(K1s[q] & 1023u);
                sidx2[vs[q]] = (int)(K2s[q] & 1023u);
                int fq = (m3 - m1 < MARGIN) ? 2 : ((m2 - m1 < MARGIN) ? 1 : 0);
                sflg[vs[q]] = fq;
                if (fq == 2) { int p = atomicAdd(nlist, 1); list[p] = vs[q]; }
            }
        }
        __syncthreads();

        // ---- full exact rescans (rare) ----
        int nf = *nlist;
        for (int f = 0; f < nf; ++f) {
            int vr = list[f];
            if (tid == 0) *redk = ~0ull;
            if (v == vr) {
                const float4* rp4 = (const float4*)rsrc;
                #pragma unroll
                for (int i = 0; i < 16; ++i)
                    *(float4*)(rstage + 4*i) = rp4[i];
            }
            __syncthreads();
            unsigned long long bk = ~0ull;
            #pragma unroll 1
            for (int c = tid; c < KCB; c += NTHR) {
                const float4* cw = (const float4*)(cb + ((size_t)l * KCB + c) * DIM);
                const float4* rp = (const float4*)rstage;
                float s = 0.f;
                #pragma unroll
                for (int i = 0; i < 16; ++i) {
                    float4 a = rp[i], bq = cw[i];
                    s += a.x*bq.x + a.y*bq.y + a.z*bq.z + a.w*bq.w;
                }
                float dist = fmaf(-2.f, s, g_c2[l * KCB + c]);
                uint32_t fb = __float_as_uint(dist);
                fb ^= (fb & 0x80000000u) ? 0xFFFFFFFFu : 0x80000000u;
                unsigned long long key = ((unsigned long long)fb << 32) | (unsigned)c;
                if (key < bk) bk = key;
            }
            atomicMin(redk, bk);
            __syncthreads();
            if (tid == 0) sidx[vr] = (int)(*redk & 0xffffffffu);
            __syncthreads();
        }

        // ---- exact duels (each flagged vector's owner thread, full dot) ----
        int idx = sidx[v];
        int fl  = sflg[v];
        if (fl == 1) {
            int iA = idx, iB = sidx2[v];
            const float4* rp4 = (const float4*)rsrc;
            const float4* ca = (const float4*)(cb + ((size_t)l * KCB + iA) * DIM);
            const float4* cbq = (const float4*)(cb + ((size_t)l * KCB + iB) * DIM);
            float sA = 0.f, sB = 0.f;
            #pragma unroll
            for (int i = 0; i < 16; ++i) {
                float4 rv = rp4[i], a = ca[i], b = cbq[i];
                sA += rv.x*a.x + rv.y*a.y + rv.z*a.z + rv.w*a.w;
                sB += rv.x*b.x + rv.y*b.y + rv.z*b.z + rv.w*b.w;
            }
            float dA = fmaf(-2.f, sA, g_c2[l * KCB + iA]);
            float dB = fmaf(-2.f, sB, g_c2[l * KCB + iB]);
            idx = lexless(dB, iB, dA, iA) ? iB : iA;
        }

        // ---- commit: r_new = r - q -> g_res; stage next A; losses; codes ----
        {
            const float4* rp4 = (const float4*)rsrc;
            const float4* q4  = (const float4*)(cb + ((size_t)l * KCB + idx) * DIM);
            float4* dst = (float4*)(g_res + roff);
            float sse = 0.f;
            #pragma unroll
            for (int i = 0; i < 16; ++i) {
                float4 rv = rp4[i], qv = q4[i];
                float4 rn = make_float4(rv.x - qv.x, rv.y - qv.y,
                                        rv.z - qv.z, rv.w - qv.w);
                sse += rn.x*rn.x + rn.y*rn.y + rn.z*rn.z + rn.w*rn.w;
                dst[i] = rn;
                if (l < LEVELS - 1) {
                    #pragma unroll
                    for (int j = 0; j < 2; ++j) {
                        int ip = 2 * i + j;
                        float lo = j ? rn.z : rn.x, hi = j ? rn.w : rn.y;
                        __nv_bfloat16 h0 = __float2bfloat16(lo);
                        __nv_bfloat16 h1 = __float2bfloat16(hi);
                        uint32_t wh = (uint32_t)__bfloat16_as_ushort(h0) |
                                      ((uint32_t)__bfloat16_as_ushort(h1) << 16);
                        int chunk = (ip >> 2) ^ (v & 7);
                        *(uint32_t*)(smem + SM_AH + v * 128 + chunk * 16 + (ip & 3) * 4) = wh;
                    }
                }
            }
            double ds = (double)sse;
            #pragma unroll
            for (int o = 16; o; o >>= 1) ds += __shfl_down_sync(0xffffffffu, ds, o);
            if (lane == 0) atomicAdd(&g_mse[l], ds);
        }
        atomicAdd(&g_counts[l * KCB + idx], 1);
        out[QELEMS + (size_t)l * NVEC + n0 + v] = (float)idx;
        __syncthreads();
    }
}

// ---------------- epilogue: quantized = x - final residual ----------------
__global__ void out_kernel(const float* __restrict__ x, float* __restrict__ out) {
    size_t i = (size_t)blockIdx.x * blockDim.x + threadIdx.x;
    size_t stride = (size_t)gridDim.x * blockDim.x;
    const float4* x4 = (const float4*)x;
    const float4* r4 = (const float4*)g_res;
    float4* o4 = (float4*)out;
    for (size_t g = i; g < QELEMS / 4; g += stride) {
        float4 xv = x4[g], rv = r4[g];
        o4[g] = make_float4(xv.x - rv.x, xv.y - rv.y, xv.z - rv.z, xv.w - rv.w);
    }
}

__global__ void finalize_kernel(float* __restrict__ out) {
    __shared__ double warpsum[8];
    const int t = threadIdx.x;
    double total = 0.0;
    for (int l = 0; l < LEVELS; ++l) {
        float esum = 0.f;
        for (int i = t; i < KCB; i += 256) {
            float p = (float)g_counts[l * KCB + i] / (float)NVEC;
            esum += -(p * logf(p + 1e-10f));
        }
        double e = (double)esum;
        #pragma unroll
        for (int o = 16; o; o >>= 1) e += __shfl_down_sync(0xffffffffu, e, o);
        if ((t & 31) == 0) warpsum[t >> 5] = e;
        __syncthreads();
        if (t == 0) {
            double ent = 0.0;
            #pragma unroll
            for (int w = 0; w < 8; ++w) ent += warpsum[w];
            total += 1.25 * (g_mse[l] / ((double)NVEC * DIM)) + 0.1 * ent;
        }
        __syncthreads();
    }
    if (t == 0) out[QELEMS + (size_t)LEVELS * NVEC] = (float)total;
}

extern "C" void kernel_launch(void* const* d_in, const int* in_sizes, int n_in,
                              void* d_out, int out_size) {
    const float* x  = (const float*)d_in[0];
    const float* cb = (const float*)d_in[1];
    float* out = (float*)d_out;

    cudaFuncSetAttribute(rvq_mma_kernel,
                         cudaFuncAttributeMaxDynamicSharedMemorySize, SMEM_TOTAL);

    prep_kernel<<<16, 256>>>(cb);
    rvq_mma_kernel<<<NVEC / CTAV, NTHR, SMEM_TOTAL>>>(x, cb, out);
    out_kernel<<<512, 256>>>(x, out);
    finalize_kernel<<<1, 256>>>(out);
}